// round 16
// baseline (speedup 1.0000x reference)
#include <cuda_runtime.h>
#include <cuda_fp16.h>
#include <math.h>
#include <cstdint>

#define D_MODEL 1024
#define SEQ     2048
#define BATCH   4
#define NH      16
#define HD      64
#define ROWS    (BATCH * SEQ)   // 8192

// ---------------------------------------------------------------------------
// Device-global scratch (no runtime allocation allowed)
// Weights stored pre-scaled by 32 (un-scaled in fp32 epilogues) so that the
// fp16 lo-correction terms stay in normal range.
// ---------------------------------------------------------------------------
__device__ float g_emb[SEQ * HD];
__device__ __half g_qh[ROWS * D_MODEL];   // Q (rot, /8) hi only   [b,h,s,d]
__device__ __half g_kh[ROWS * D_MODEL];   // K (rot) hi            [b,h,s,d]
__device__ __half g_kl[ROWS * D_MODEL];   // K lo
__device__ __half g_vth[ROWS * D_MODEL];  // V hi TRANSPOSED       [b,h,d,s]
__device__ __half g_vtl[ROWS * D_MODEL];  // V lo
__device__ __half g_xh[ROWS * D_MODEL];   // ln(x) hi only
__device__ __half g_ah[ROWS * D_MODEL];   // attention out hi only
__device__ __half g_wh[4 * D_MODEL * D_MODEL];  // 32*W hi (q,k,v,out)
__device__ __half g_wl[4 * D_MODEL * D_MODEL];  // 32*W lo

// ---------------------------------------------------------------------------
// PTX helpers
// ---------------------------------------------------------------------------
__device__ __forceinline__ uint32_t smem_to_u32(const void* smem_ptr) {
    uint32_t addr;
    asm("{ .reg .u64 tmp; cvta.to.shared.u64 tmp, %1; cvt.u32.u64 %0, tmp; }"
        : "=r"(addr) : "l"(smem_ptr));
    return addr;
}
__device__ __forceinline__ void ldm_x4(uint32_t* r, uint32_t addr) {
    asm volatile("ldmatrix.sync.aligned.m8n8.x4.shared.b16 {%0,%1,%2,%3}, [%4];"
        : "=r"(r[0]), "=r"(r[1]), "=r"(r[2]), "=r"(r[3]) : "r"(addr));
}
__device__ __forceinline__ void mma_f16(float* c, const uint32_t* a, const uint32_t* b) {
    asm volatile(
        "mma.sync.aligned.m16n8k16.row.col.f32.f16.f16.f32 "
        "{%0,%1,%2,%3}, {%4,%5,%6,%7}, {%8,%9}, {%0,%1,%2,%3};"
        : "+f"(c[0]), "+f"(c[1]), "+f"(c[2]), "+f"(c[3])
        : "r"(a[0]), "r"(a[1]), "r"(a[2]), "r"(a[3]), "r"(b[0]), "r"(b[1]));
}
__device__ __forceinline__ void cp_async16(uint32_t smem, const void* gptr) {
    asm volatile("cp.async.cg.shared.global [%0], [%1], 16;"
        :: "r"(smem), "l"(gptr));
}
#define CP_COMMIT() asm volatile("cp.async.commit_group;" ::: "memory")
#define CP_WAIT0()  asm volatile("cp.async.wait_group 0;" ::: "memory")

__device__ __forceinline__ uint32_t pack_f16x2(float lo, float hi) {
    __half2 p = __floats2half2_rn(lo, hi);
    return *(uint32_t*)&p;
}

// ---------------------------------------------------------------------------
// Fused prep: rotary emb table + weight hi/lo split (x32) + LayerNorm
// grid sections: [0,512) emb | [512,16896) wconv | [16896,25088) ln
// ---------------------------------------------------------------------------
#define PREP_EMB_BLKS   ((SEQ * HD) / 256)              // 512
#define PREP_W_BLKS     ((4 * D_MODEL * D_MODEL) / 256) // 16384
#define PREP_LN_BLKS    ROWS                            // 8192
#define PREP_BLKS       (PREP_EMB_BLKS + PREP_W_BLKS + PREP_LN_BLKS)

__global__ __launch_bounds__(256) void prep_kernel(const float* __restrict__ x,
                                                   const float* __restrict__ lng,
                                                   const float* __restrict__ lnb,
                                                   const float* __restrict__ qw,
                                                   const float* __restrict__ kw,
                                                   const float* __restrict__ vw,
                                                   const float* __restrict__ ow) {
    int bid = blockIdx.x;
    int tid = threadIdx.x;
    if (bid < PREP_EMB_BLKS) {
        int idx = bid * 256 + tid;
        int s = idx >> 6;
        int d = idx & 63;
        int i = d & 31;
        double f = exp(-log(10000.0) * (double)i / 32.0);
        double a = (double)s * f;
        g_emb[idx] = (d < 32) ? (float)sin(a) : (float)cos(a);
        return;
    }
    bid -= PREP_EMB_BLKS;
    if (bid < PREP_W_BLKS) {
        int i = bid * 256 + tid;
        int m = i >> 20;
        const float* src = (m == 0) ? qw : (m == 1) ? kw : (m == 2) ? vw : ow;
        float val = src[i & 0xFFFFF] * 32.f;
        __half h = __float2half(val);
        g_wh[i] = h;
        g_wl[i] = __float2half(val - __half2float(h));
        return;
    }
    bid -= PREP_W_BLKS;
    {
        int row = bid;
        const float* xr = x + (size_t)row * D_MODEL;
        float4 v = *(const float4*)(xr + tid * 4);
        float s1 = v.x + v.y + v.z + v.w;
        float s2 = v.x * v.x + v.y * v.y + v.z * v.z + v.w * v.w;
#pragma unroll
        for (int off = 16; off; off >>= 1) {
            s1 += __shfl_xor_sync(0xffffffffu, s1, off);
            s2 += __shfl_xor_sync(0xffffffffu, s2, off);
        }
        __shared__ float r1[8], r2[8];
        int w = tid >> 5, lane = tid & 31;
        if (lane == 0) { r1[w] = s1; r2[w] = s2; }
        __syncthreads();
        float t1 = 0.f, t2 = 0.f;
#pragma unroll
        for (int i = 0; i < 8; i++) { t1 += r1[i]; t2 += r2[i]; }
        float mu   = t1 * (1.f / D_MODEL);
        float var  = t2 * (1.f / D_MODEL) - mu * mu;
        float rstd = rsqrtf(var + 1e-5f);
        float4 gv = *(const float4*)(lng + tid * 4);
        float4 bv = *(const float4*)(lnb + tid * 4);
        float o0 = (v.x - mu) * rstd * gv.x + bv.x;
        float o1 = (v.y - mu) * rstd * gv.y + bv.y;
        float o2 = (v.z - mu) * rstd * gv.z + bv.z;
        float o3 = (v.w - mu) * rstd * gv.w + bv.w;
        size_t base = (size_t)row * D_MODEL + tid * 4;
        *(__half2*)&g_xh[base]     = __floats2half2_rn(o0, o1);
        *(__half2*)&g_xh[base + 2] = __floats2half2_rn(o2, o3);
    }
}

// ---------------------------------------------------------------------------
// HMMA fp16 2-term GEMM:  C[128x128 tile] = A[M,1024] @ (32W)[N,1024]^T / 32
//   C = Ah*Wh + Ah*Wl   (residual Al*W ~ 2^-11 relative)
// smem: Ah, Wh, Wl (3 matrices). Single barrier per chunk.
// mode 0: QKV (+rot, q scaled /8, v transposed); mode 1: out-proj.
// ---------------------------------------------------------------------------
#define BM 128
#define BN 128
#define BK 32
#define ROWB 80                          // padded smem row bytes (32 fp16 + pad)
#define MAT_BYTES (128 * ROWB)           // 10240
#define BUF_BYTES (3 * MAT_BYTES)        // Ah, Wh, Wl
#define GEMM_SMEM (2 * BUF_BYTES)        // 61440

__global__ __launch_bounds__(256) void mma_gemm_kernel(int mode,
                                                       const float* __restrict__ bias,
                                                       const float* __restrict__ xres,
                                                       float* __restrict__ outp) {
    extern __shared__ char dsm[];
    uint32_t s0 = smem_to_u32(dsm);
    int tid = threadIdx.x, lane = tid & 31, wid = tid >> 5;
    int wm = wid >> 2, wn = wid & 3;
    int z = blockIdx.z;
    int row0 = blockIdx.y * BM;
    int col0 = blockIdx.x * BN;

    const __half* Ah = (mode == 0) ? g_xh : g_ah;
    int widx = (mode == 0) ? z : 3;
    const __half* Wh = g_wh + (size_t)widx * D_MODEL * D_MODEL;
    const __half* Wl = g_wl + (size_t)widx * D_MODEL * D_MODEL;

    float C[4][4][4];
#pragma unroll
    for (int mi = 0; mi < 4; mi++)
#pragma unroll
        for (int nj = 0; nj < 4; nj++)
#pragma unroll
            for (int q = 0; q < 4; q++) C[mi][nj][q] = 0.f;

    int lr_ = tid >> 2, lcu = tid & 3;            // row 0..63, 16B unit 0..3
    uint32_t sA = (uint32_t)(lr_ * ROWB + lcu * 16);
    size_t gAoff = (size_t)lr_ * D_MODEL + lcu * 8;

    auto load_chunk = [&](int c, int bi) {
        int kt = c * BK;
        uint32_t sb = s0 + bi * BUF_BYTES;
        const __half* pAh = Ah + (size_t)row0 * D_MODEL + kt + gAoff;
        const __half* pWh = Wh + (size_t)col0 * D_MODEL + kt + gAoff;
        const __half* pWl = Wl + (size_t)col0 * D_MODEL + kt + gAoff;
        const size_t rstep = (size_t)64 * D_MODEL;
        cp_async16(sb + sA,                             pAh);
        cp_async16(sb + sA + 64 * ROWB,                 pAh + rstep);
        cp_async16(sb + MAT_BYTES + sA,                 pWh);
        cp_async16(sb + MAT_BYTES + sA + 64 * ROWB,     pWh + rstep);
        cp_async16(sb + 2 * MAT_BYTES + sA,             pWl);
        cp_async16(sb + 2 * MAT_BYTES + sA + 64 * ROWB, pWl + rstep);
    };

    int amat = lane >> 3;                       // 0..3
    int mrow = (amat & 1) * 8 + (lane & 7);     // row offset within 16-row tile
    int mcu  = amat >> 1;                       // k-unit (16B) offset

    load_chunk(0, 0);
    CP_COMMIT();

    for (int c = 0; c < 32; c++) {
        int bi = c & 1;
        CP_WAIT0();
        __syncthreads();
        if (c < 32 - 1) { load_chunk(c + 1, bi ^ 1); CP_COMMIT(); }

        uint32_t ahB = s0 + bi * BUF_BYTES;
        uint32_t whB = ahB + MAT_BYTES;
        uint32_t wlB = ahB + 2 * MAT_BYTES;

#pragma unroll
        for (int ks = 0; ks < 2; ks++) {
            int k0u = ks * 2;
            uint32_t fa[4][4];
#pragma unroll
            for (int mi = 0; mi < 4; mi++) {
                uint32_t off = (uint32_t)((wm * 64 + mi * 16 + mrow) * ROWB +
                                          (k0u + mcu) * 16);
                ldm_x4(fa[mi], ahB + off);
            }
            uint32_t fb_h[2][4], fb_l[2][4];
#pragma unroll
            for (int hf = 0; hf < 2; hf++) {
                uint32_t off = (uint32_t)((wn * 32 + hf * 16 + mrow) * ROWB +
                                          (k0u + mcu) * 16);
                ldm_x4(fb_h[hf], whB + off);
                ldm_x4(fb_l[hf], wlB + off);
            }
            // Pass 1: Ah * Wh
#pragma unroll
            for (int mi = 0; mi < 4; mi++)
#pragma unroll
                for (int nj = 0; nj < 4; nj++) {
                    int hf = nj >> 1, lo = nj & 1;
                    uint32_t bv[2] = {fb_h[hf][lo], fb_h[hf][lo + 2]};
                    mma_f16(C[mi][nj], fa[mi], bv);
                }
            // Pass 2: Ah * Wl
#pragma unroll
            for (int mi = 0; mi < 4; mi++)
#pragma unroll
                for (int nj = 0; nj < 4; nj++) {
                    int hf = nj >> 1, lo = nj & 1;
                    uint32_t bv[2] = {fb_l[hf][lo], fb_l[hf][lo + 2]};
                    mma_f16(C[mi][nj], fa[mi], bv);
                }
        }
    }

    // Epilogue (fp32 un-scale by 1/32)
    const float inv32 = 1.f / 32.f;
    int g = lane >> 2, t = lane & 3;
#pragma unroll
    for (int mi = 0; mi < 4; mi++) {
#pragma unroll
        for (int nj = 0; nj < 4; nj++) {
            int cbase = col0 + wn * 32 + nj * 8 + t * 2;
#pragma unroll
            for (int rr = 0; rr < 2; rr++) {
                int r = row0 + wm * 64 + mi * 16 + g + rr * 8;
                float vx = C[mi][nj][rr * 2 + 0] * inv32;
                float vy = C[mi][nj][rr * 2 + 1] * inv32;
                if (mode == 0) {
                    int b = r >> 11, s = r & 2047, h = cbase >> 6, dd = cbase & 63;
                    if (z < 2) {
                        vx *= g_emb[s * HD + dd];
                        vy *= g_emb[s * HD + dd + 1];
                        if (z == 0) { vx *= 0.125f; vy *= 0.125f; }
                    }
                    __half hx = __float2half(vx);
                    __half hy = __float2half(vy);
                    if (z == 0) {
                        size_t ib = ((size_t)(b * NH + h) * SEQ + s) * HD + dd;
                        *(__half2*)&g_qh[ib] = __half2(hx, hy);
                    } else if (z == 1) {
                        size_t ib = ((size_t)(b * NH + h) * SEQ + s) * HD + dd;
                        *(__half2*)&g_kh[ib] = __half2(hx, hy);
                        *(__half2*)&g_kl[ib] =
                            __floats2half2_rn(vx - __half2float(hx),
                                              vy - __half2float(hy));
                    } else {
                        // transposed V: [b,h,d,s]
                        size_t tb = ((size_t)(b * NH + h) * HD + dd) * SEQ + s;
                        g_vth[tb] = hx;
                        g_vtl[tb] = __float2half(vx - __half2float(hx));
                        g_vth[tb + SEQ] = hy;
                        g_vtl[tb + SEQ] = __float2half(vy - __half2float(hy));
                    }
                } else {
                    float2 bv = *(const float2*)&bias[cbase];
                    float2 xv = *(const float2*)&xres[(size_t)r * D_MODEL + cbase];
                    float2 v;
                    v.x = vx + bv.x + xv.x;
                    v.y = vy + bv.y + xv.y;
                    *(float2*)&outp[(size_t)r * D_MODEL + cbase] = v;
                }
            }
        }
    }
}

// ---------------------------------------------------------------------------
// HMMA fp16 flash attention: 128 q-rows/CTA, 64-key tiles, 8 warps.
// S = Qh*(Kh+Kl)^T (2-term); O += Ph*(Vh+Vl) (2-term, V pre-transposed).
// Double-buffered K/V/mask; one __syncthreads per kt; heavy-first qt order.
// ---------------------------------------------------------------------------
#define FP 144                            // smem row pitch bytes (64 fp16 + 8 pad)
#define FQH_B 0
#define KV0_B (128 * FP)                  // 18432
#define KVSTAGE_B (4 * 64 * FP)           // 36864
#define KH_OFF 0
#define KL_OFF (64 * FP)
#define VH_OFF (2 * 64 * FP)
#define VL_OFF (3 * 64 * FP)
#define FMS_B (KV0_B + 2 * KVSTAGE_B)     // 92160
#define FLASH_SMEM (FMS_B + 2 * 64 * 4)   // 92672

__global__ __launch_bounds__(256) void flash_mma_kernel(const unsigned char* __restrict__ kpm) {
    extern __shared__ char fsm[];
    uint32_t s0 = smem_to_u32(fsm);
    float* Ms = (float*)(fsm + FMS_B);

    int tid = threadIdx.x, lane = tid & 31, wid = tid >> 5;
    int qt = (int)gridDim.x - 1 - (int)blockIdx.x;   // heavy tiles first
    int bh = blockIdx.y;            // 0..63
    int b = bh >> 4, h = bh & 15;
    int q0 = qt * 128;

    int g = lane >> 2, t4 = lane & 3;
    int amat = lane >> 3;
    int mrow = (amat & 1) * 8 + (lane & 7);
    int mcu  = amat >> 1;

    auto load_kv = [&](int kt, int stage) {
        int k0 = kt * 64;
        uint32_t kb = s0 + KV0_B + stage * KVSTAGE_B;
#pragma unroll
        for (int t = 0; t < 2; t++) {
            int u = tid + t * 256;      // 0..511
            int r = u >> 3, cu = u & 7;
            size_t ki = ((size_t)bh * SEQ + k0 + r) * HD + cu * 8;
            size_t vi = ((size_t)bh * HD + r) * SEQ + k0 + cu * 8;
            cp_async16(kb + KH_OFF + r * FP + cu * 16, g_kh + ki);
            cp_async16(kb + KL_OFF + r * FP + cu * 16, g_kl + ki);
            cp_async16(kb + VH_OFF + r * FP + cu * 16, g_vth + vi);
            cp_async16(kb + VL_OFF + r * FP + cu * 16, g_vtl + vi);
        }
    };

    // Initial: Q tile (hi only) + KV stage 0 + mask slot 0
#pragma unroll
    for (int t = 0; t < 4; t++) {
        int u = tid + t * 256;          // 0..1023
        int r = u >> 3, cu = u & 7;
        size_t gi = ((size_t)bh * SEQ + q0 + r) * HD + cu * 8;
        cp_async16(s0 + FQH_B + r * FP + cu * 16, g_qh + gi);
    }
    load_kv(0, 0);
    if (tid < 64) Ms[tid] = kpm[b * SEQ + tid] ? -1e30f : 0.f;
    CP_COMMIT();

    float mr[2] = {-INFINITY, -INFINITY};
    float lr[2] = {0.f, 0.f};
    float O[8][4];
#pragma unroll
    for (int j = 0; j < 8; j++)
#pragma unroll
        for (int q = 0; q < 4; q++) O[j][q] = 0.f;

    int rowg = q0 + wid * 16 + g;       // this thread's first q row

    int ktmax = (q0 + 127) >> 6;
    for (int kt = 0; kt <= ktmax; kt++) {
        int bi = kt & 1;
        int k0 = kt * 64;
        CP_WAIT0();
        __syncthreads();
        if (kt < ktmax) {
            load_kv(kt + 1, bi ^ 1);
            CP_COMMIT();
            if (tid < 64)
                Ms[(bi ^ 1) * 64 + tid] =
                    kpm[b * SEQ + (kt + 1) * 64 + tid] ? -1e30f : 0.f;
        }
        uint32_t kvb = s0 + KV0_B + bi * KVSTAGE_B;
        float* Msl = Ms + bi * 64;

        // ---- S = Qh K^T (2-term) ----
        float S[8][4];
#pragma unroll
        for (int j = 0; j < 8; j++)
#pragma unroll
            for (int q = 0; q < 4; q++) S[j][q] = 0.f;

#pragma unroll
        for (int ks = 0; ks < 4; ks++) {
            uint32_t qh[4];
            uint32_t qoff = (uint32_t)((wid * 16 + mrow) * FP + ks * 32 + mcu * 16);
            ldm_x4(qh, s0 + FQH_B + qoff);
            uint32_t kh[4][4], kl[4][4];
#pragma unroll
            for (int grp = 0; grp < 4; grp++) {
                uint32_t koff = (uint32_t)((grp * 16 + mrow) * FP + ks * 32 + mcu * 16);
                ldm_x4(kh[grp], kvb + KH_OFF + koff);
                ldm_x4(kl[grp], kvb + KL_OFF + koff);
            }
#pragma unroll
            for (int j = 0; j < 8; j++) {
                int grp = j >> 1, lo = j & 1;
                uint32_t bv[2] = {kh[grp][lo], kh[grp][lo + 2]};
                mma_f16(S[j], qh, bv);
            }
#pragma unroll
            for (int j = 0; j < 8; j++) {
                int grp = j >> 1, lo = j & 1;
                uint32_t bv[2] = {kl[grp][lo], kl[grp][lo + 2]};
                mma_f16(S[j], qh, bv);
            }
        }

        // ---- mask + row max (no MUFU) ----
        bool needc = (k0 + 63 > q0);
#pragma unroll
        for (int j = 0; j < 8; j++) {
            int c0 = 8 * j + t4 * 2;
            float m0 = Msl[c0], m1 = Msl[c0 + 1];
            float s0v = S[j][0] + m0, s1v = S[j][1] + m1;
            float s2v = S[j][2] + m0, s3v = S[j][3] + m1;
            if (needc) {
                int kc0 = k0 + c0;
                if (kc0 > rowg)          s0v = -1e30f;
                if (kc0 + 1 > rowg)      s1v = -1e30f;
                if (kc0 > rowg + 8)      s2v = -1e30f;
                if (kc0 + 1 > rowg + 8)  s3v = -1e30f;
            }
            S[j][0] = s0v; S[j][1] = s1v; S[j][2] = s2v; S[j][3] = s3v;
        }
        float mt0 = -1e30f, mt1 = -1e30f;
#pragma unroll
        for (int j = 0; j < 8; j++) {
            mt0 = fmaxf(mt0, fmaxf(S[j][0], S[j][1]));
            mt1 = fmaxf(mt1, fmaxf(S[j][2], S[j][3]));
        }
        mt0 = fmaxf(mt0, __shfl_xor_sync(0xffffffffu, mt0, 1));
        mt0 = fmaxf(mt0, __shfl_xor_sync(0xffffffffu, mt0, 2));
        mt1 = fmaxf(mt1, __shfl_xor_sync(0xffffffffu, mt1, 1));
        mt1 = fmaxf(mt1, __shfl_xor_sync(0xffffffffu, mt1, 2));
        float mn0 = fmaxf(mr[0], mt0), mn1 = fmaxf(mr[1], mt1);
        float corr0 = __expf(mr[0] - mn0), corr1 = __expf(mr[1] - mn1);
        mr[0] = mn0; mr[1] = mn1;
#pragma unroll
        for (int j = 0; j < 8; j++) {
            O[j][0] *= corr0; O[j][1] *= corr0;
            O[j][2] *= corr1; O[j][3] *= corr1;
        }

        // ---- interleaved: exp/pack of chunk ks + PV mma (2-term) ----
        float rs0 = 0.f, rs1 = 0.f;
#pragma unroll
        for (int ks = 0; ks < 4; ks++) {
            int j0 = 2 * ks, j1 = 2 * ks + 1;
            float a0 = __expf(S[j0][0] - mn0), a1 = __expf(S[j0][1] - mn0);
            float a2 = __expf(S[j0][2] - mn1), a3 = __expf(S[j0][3] - mn1);
            float b0 = __expf(S[j1][0] - mn0), b1 = __expf(S[j1][1] - mn0);
            float b2 = __expf(S[j1][2] - mn1), b3 = __expf(S[j1][3] - mn1);
            rs0 += a0 + a1 + b0 + b1;
            rs1 += a2 + a3 + b2 + b3;
            uint32_t pah[4];
            pah[0] = pack_f16x2(a0, a1);
            pah[1] = pack_f16x2(a2, a3);
            pah[2] = pack_f16x2(b0, b1);
            pah[3] = pack_f16x2(b2, b3);
            uint32_t vh[4][4], vl[4][4];
#pragma unroll
            for (int grp = 0; grp < 4; grp++) {
                uint32_t voff = (uint32_t)((grp * 16 + mrow) * FP + ks * 32 + mcu * 16);
                ldm_x4(vh[grp], kvb + VH_OFF + voff);
                ldm_x4(vl[grp], kvb + VL_OFF + voff);
            }
#pragma unroll
            for (int jd = 0; jd < 8; jd++) {
                int grp = jd >> 1, lo = jd & 1;
                uint32_t bv[2] = {vh[grp][lo], vh[grp][lo + 2]};
                mma_f16(O[jd], pah, bv);
            }
#pragma unroll
            for (int jd = 0; jd < 8; jd++) {
                int grp = jd >> 1, lo = jd & 1;
                uint32_t bv[2] = {vl[grp][lo], vl[grp][lo + 2]};
                mma_f16(O[jd], pah, bv);
            }
        }

        // row-sum reductions off the critical path
        rs0 += __shfl_xor_sync(0xffffffffu, rs0, 1);
        rs0 += __shfl_xor_sync(0xffffffffu, rs0, 2);
        rs1 += __shfl_xor_sync(0xffffffffu, rs1, 1);
        rs1 += __shfl_xor_sync(0xffffffffu, rs1, 2);
        lr[0] = lr[0] * corr0 + rs0;
        lr[1] = lr[1] * corr1 + rs1;
    }

    // ---- epilogue: normalize, write fp16 hi to [B,S,D] for out-proj ----
    float inv0 = 1.f / lr[0], inv1 = 1.f / lr[1];
#pragma unroll
    for (int j = 0; j < 8; j++) {
        int dd = h * HD + 8 * j + t4 * 2;
        {
            size_t idx = (size_t)(b * SEQ + rowg) * D_MODEL + dd;
            *(__half2*)&g_ah[idx] =
                __floats2half2_rn(O[j][0] * inv0, O[j][1] * inv0);
        }
        {
            size_t idx = (size_t)(b * SEQ + rowg + 8) * D_MODEL + dd;
            *(__half2*)&g_ah[idx] =
                __floats2half2_rn(O[j][2] * inv1, O[j][3] * inv1);
        }
    }
}

// ---------------------------------------------------------------------------
extern "C" void kernel_launch(void* const* d_in, const int* in_sizes, int n_in,
                              void* d_out, int out_size) {
    const float* x            = (const float*)d_in[0];
    const unsigned char* kpm  = (const unsigned char*)d_in[1];
    const float* q_w          = (const float*)d_in[2];
    const float* k_w          = (const float*)d_in[3];
    const float* v_w          = (const float*)d_in[4];
    const float* out_w        = (const float*)d_in[5];
    const float* out_b        = (const float*)d_in[6];
    const float* ln_g         = (const float*)d_in[7];
    const float* ln_b         = (const float*)d_in[8];
    float* out = (float*)d_out;

    cudaFuncSetAttribute(flash_mma_kernel, cudaFuncAttributeMaxDynamicSharedMemorySize, FLASH_SMEM);
    cudaFuncSetAttribute(mma_gemm_kernel, cudaFuncAttributeMaxDynamicSharedMemorySize, GEMM_SMEM);

    prep_kernel<<<PREP_BLKS, 256>>>(x, ln_g, ln_b, q_w, k_w, v_w, out_w);
    mma_gemm_kernel<<<dim3(D_MODEL / BN, ROWS / BM, 3), 256, GEMM_SMEM>>>(
        0, nullptr, nullptr, nullptr);
    flash_mma_kernel<<<dim3(16, 64), 256, FLASH_SMEM>>>(kpm);
    mma_gemm_kernel<<<dim3(D_MODEL / BN, ROWS / BM, 1), 256, GEMM_SMEM>>>(
        1, out_b, x, out);
}

// round 17
// speedup vs baseline: 1.1793x; 1.1793x over previous
#include <cuda_runtime.h>
#include <cuda_bf16.h>
#include <cuda_fp16.h>
#include <math.h>
#include <cstdint>

#define D_MODEL 1024
#define SEQ     2048
#define BATCH   4
#define NH      16
#define HD      64
#define ROWS    (BATCH * SEQ)   // 8192

// ---------------------------------------------------------------------------
// Device-global scratch (no runtime allocation allowed)
// ---------------------------------------------------------------------------
__device__ float g_emb[SEQ * HD];
__device__ __half g_qh[ROWS * D_MODEL];          // Q (rot, /8) fp16 hi   [b,h,s,d]
__device__ __half g_kh[ROWS * D_MODEL];          // K (rot) fp16 hi       [b,h,s,d]
__device__ __half g_kl[ROWS * D_MODEL];          // K fp16 lo
__device__ __half g_vth[ROWS * D_MODEL];         // V fp16 hi TRANSPOSED  [b,h,d,s]
__device__ __half g_vtl[ROWS * D_MODEL];         // V fp16 lo
__device__ __nv_bfloat16 g_xh[ROWS * D_MODEL];   // ln(x) bf16 hi
__device__ __nv_bfloat16 g_xl[ROWS * D_MODEL];   // ln(x) bf16 lo
__device__ __nv_bfloat16 g_ah[ROWS * D_MODEL];   // attention out bf16 hi
__device__ __nv_bfloat16 g_al[ROWS * D_MODEL];   // attention out bf16 lo
__device__ __nv_bfloat16 g_wh[4 * D_MODEL * D_MODEL];  // q,k,v,out weights hi
__device__ __nv_bfloat16 g_wl[4 * D_MODEL * D_MODEL];  // lo

// ---------------------------------------------------------------------------
// PTX helpers
// ---------------------------------------------------------------------------
__device__ __forceinline__ uint32_t smem_to_u32(const void* smem_ptr) {
    uint32_t addr;
    asm("{ .reg .u64 tmp; cvta.to.shared.u64 tmp, %1; cvt.u32.u64 %0, tmp; }"
        : "=r"(addr) : "l"(smem_ptr));
    return addr;
}
__device__ __forceinline__ void ldm_x4(uint32_t* r, uint32_t addr) {
    asm volatile("ldmatrix.sync.aligned.m8n8.x4.shared.b16 {%0,%1,%2,%3}, [%4];"
        : "=r"(r[0]), "=r"(r[1]), "=r"(r[2]), "=r"(r[3]) : "r"(addr));
}
__device__ __forceinline__ void mma_bf16(float* c, const uint32_t* a, const uint32_t* b) {
    asm volatile(
        "mma.sync.aligned.m16n8k16.row.col.f32.bf16.bf16.f32 "
        "{%0,%1,%2,%3}, {%4,%5,%6,%7}, {%8,%9}, {%0,%1,%2,%3};"
        : "+f"(c[0]), "+f"(c[1]), "+f"(c[2]), "+f"(c[3])
        : "r"(a[0]), "r"(a[1]), "r"(a[2]), "r"(a[3]), "r"(b[0]), "r"(b[1]));
}
__device__ __forceinline__ void mma_f16(float* c, const uint32_t* a, const uint32_t* b) {
    asm volatile(
        "mma.sync.aligned.m16n8k16.row.col.f32.f16.f16.f32 "
        "{%0,%1,%2,%3}, {%4,%5,%6,%7}, {%8,%9}, {%0,%1,%2,%3};"
        : "+f"(c[0]), "+f"(c[1]), "+f"(c[2]), "+f"(c[3])
        : "r"(a[0]), "r"(a[1]), "r"(a[2]), "r"(a[3]), "r"(b[0]), "r"(b[1]));
}
__device__ __forceinline__ void cp_async16(uint32_t smem, const void* gptr) {
    asm volatile("cp.async.cg.shared.global [%0], [%1], 16;"
        :: "r"(smem), "l"(gptr));
}
#define CP_COMMIT() asm volatile("cp.async.commit_group;" ::: "memory")
#define CP_WAIT0()  asm volatile("cp.async.wait_group 0;" ::: "memory")

__device__ __forceinline__ uint32_t pack_f16x2(float lo, float hi) {
    __half2 p = __floats2half2_rn(lo, hi);
    return *(uint32_t*)&p;
}

// ---------------------------------------------------------------------------
// Rotary emb table (double precision — args reach ~2048 rad)
// ---------------------------------------------------------------------------
__global__ __launch_bounds__(256) void emb_kernel() {
    int idx = blockIdx.x * 256 + threadIdx.x;   // 0 .. SEQ*HD-1
    int s = idx >> 6;
    int d = idx & 63;
    int i = d & 31;
    double f = exp(-log(10000.0) * (double)i / 32.0);
    double a = (double)s * f;
    g_emb[idx] = (d < 32) ? (float)sin(a) : (float)cos(a);
}

// ---------------------------------------------------------------------------
// Weight hi/lo bf16 split: 4 x 1024x1024
// ---------------------------------------------------------------------------
__global__ __launch_bounds__(256) void wconv_kernel(const float* __restrict__ q,
                                                    const float* __restrict__ k,
                                                    const float* __restrict__ v,
                                                    const float* __restrict__ o) {
    int i = blockIdx.x * 256 + threadIdx.x;   // 0 .. 4M-1
    int m = i >> 20;
    const float* src = (m == 0) ? q : (m == 1) ? k : (m == 2) ? v : o;
    float val = src[i & 0xFFFFF];
    __nv_bfloat16 h = __float2bfloat16(val);
    g_wh[i] = h;
    g_wl[i] = __float2bfloat16(val - __bfloat162float(h));
}

// ---------------------------------------------------------------------------
// LayerNorm fused with bf16 hi/lo split output
// ---------------------------------------------------------------------------
__global__ __launch_bounds__(256) void ln_kernel(const float* __restrict__ x,
                                                 const float* __restrict__ g,
                                                 const float* __restrict__ b) {
    int row = blockIdx.x;
    int tid = threadIdx.x;
    const float* xr = x + (size_t)row * D_MODEL;
    float4 v = *(const float4*)(xr + tid * 4);
    float s1 = v.x + v.y + v.z + v.w;
    float s2 = v.x * v.x + v.y * v.y + v.z * v.z + v.w * v.w;
#pragma unroll
    for (int off = 16; off; off >>= 1) {
        s1 += __shfl_xor_sync(0xffffffffu, s1, off);
        s2 += __shfl_xor_sync(0xffffffffu, s2, off);
    }
    __shared__ float r1[8], r2[8];
    int w = tid >> 5, lane = tid & 31;
    if (lane == 0) { r1[w] = s1; r2[w] = s2; }
    __syncthreads();
    float t1 = 0.f, t2 = 0.f;
#pragma unroll
    for (int i = 0; i < 8; i++) { t1 += r1[i]; t2 += r2[i]; }
    float mu   = t1 * (1.f / D_MODEL);
    float var  = t2 * (1.f / D_MODEL) - mu * mu;
    float rstd = rsqrtf(var + 1e-5f);
    float4 gv = *(const float4*)(g + tid * 4);
    float4 bv = *(const float4*)(b + tid * 4);
    float o0 = (v.x - mu) * rstd * gv.x + bv.x;
    float o1 = (v.y - mu) * rstd * gv.y + bv.y;
    float o2 = (v.z - mu) * rstd * gv.z + bv.z;
    float o3 = (v.w - mu) * rstd * gv.w + bv.w;
    size_t base = (size_t)row * D_MODEL + tid * 4;
    __nv_bfloat16 h0 = __float2bfloat16(o0), h1 = __float2bfloat16(o1);
    __nv_bfloat16 h2 = __float2bfloat16(o2), h3 = __float2bfloat16(o3);
    *(__nv_bfloat162*)&g_xh[base]     = __nv_bfloat162(h0, h1);
    *(__nv_bfloat162*)&g_xh[base + 2] = __nv_bfloat162(h2, h3);
    *(__nv_bfloat162*)&g_xl[base] =
        __nv_bfloat162(__float2bfloat16(o0 - __bfloat162float(h0)),
                       __float2bfloat16(o1 - __bfloat162float(h1)));
    *(__nv_bfloat162*)&g_xl[base + 2] =
        __nv_bfloat162(__float2bfloat16(o2 - __bfloat162float(h2)),
                       __float2bfloat16(o3 - __bfloat162float(h3)));
}

// ---------------------------------------------------------------------------
// HMMA bf16 3-term GEMM (R13-proven):  C = Ah*Wh + Ah*Wl + Al*Wh
// Single barrier per chunk. mode 0: QKV -> fp16 q(hi)/k(hi,lo)/v^T(hi,lo);
// mode 1: out-proj (bias + residual -> d_out).
// ---------------------------------------------------------------------------
#define BM 128
#define BN 128
#define BK 32
#define ROWB 80
#define MAT_BYTES (128 * ROWB)           // 10240
#define BUF_BYTES (4 * MAT_BYTES)        // Ah, Al, Wh, Wl
#define GEMM_SMEM (2 * BUF_BYTES)        // 81920

__global__ __launch_bounds__(256) void mma_gemm_kernel(int mode,
                                                       const float* __restrict__ bias,
                                                       const float* __restrict__ xres,
                                                       float* __restrict__ outp) {
    extern __shared__ char dsm[];
    uint32_t s0 = smem_to_u32(dsm);
    int tid = threadIdx.x, lane = tid & 31, wid = tid >> 5;
    int wm = wid >> 2, wn = wid & 3;
    int z = blockIdx.z;
    int row0 = blockIdx.y * BM;
    int col0 = blockIdx.x * BN;

    const __nv_bfloat16* Ah = (mode == 0) ? g_xh : g_ah;
    const __nv_bfloat16* Al = (mode == 0) ? g_xl : g_al;
    int widx = (mode == 0) ? z : 3;
    const __nv_bfloat16* Wh = g_wh + (size_t)widx * D_MODEL * D_MODEL;
    const __nv_bfloat16* Wl = g_wl + (size_t)widx * D_MODEL * D_MODEL;

    float C[4][4][4];
#pragma unroll
    for (int mi = 0; mi < 4; mi++)
#pragma unroll
        for (int nj = 0; nj < 4; nj++)
#pragma unroll
            for (int q = 0; q < 4; q++) C[mi][nj][q] = 0.f;

    int lr_ = tid >> 2, lcu = tid & 3;            // row 0..63, 16B unit 0..3
    uint32_t sA = (uint32_t)(lr_ * ROWB + lcu * 16);
    size_t gAoff = (size_t)lr_ * D_MODEL + lcu * 8;

    auto load_chunk = [&](int c, int bi) {
        int kt = c * BK;
        uint32_t sb = s0 + bi * BUF_BYTES;
        const __nv_bfloat16* pAh = Ah + (size_t)row0 * D_MODEL + kt + gAoff;
        const __nv_bfloat16* pAl = Al + (size_t)row0 * D_MODEL + kt + gAoff;
        const __nv_bfloat16* pWh = Wh + (size_t)col0 * D_MODEL + kt + gAoff;
        const __nv_bfloat16* pWl = Wl + (size_t)col0 * D_MODEL + kt + gAoff;
        const size_t rstep = (size_t)64 * D_MODEL;
        cp_async16(sb + sA,                                   pAh);
        cp_async16(sb + sA + 64 * ROWB,                       pAh + rstep);
        cp_async16(sb + MAT_BYTES + sA,                       pAl);
        cp_async16(sb + MAT_BYTES + sA + 64 * ROWB,           pAl + rstep);
        cp_async16(sb + 2 * MAT_BYTES + sA,                   pWh);
        cp_async16(sb + 2 * MAT_BYTES + sA + 64 * ROWB,       pWh + rstep);
        cp_async16(sb + 3 * MAT_BYTES + sA,                   pWl);
        cp_async16(sb + 3 * MAT_BYTES + sA + 64 * ROWB,       pWl + rstep);
    };

    int amat = lane >> 3;
    int mrow = (amat & 1) * 8 + (lane & 7);
    int mcu  = amat >> 1;

    load_chunk(0, 0);
    CP_COMMIT();

    for (int c = 0; c < 32; c++) {
        int bi = c & 1;
        CP_WAIT0();
        __syncthreads();
        if (c < 32 - 1) { load_chunk(c + 1, bi ^ 1); CP_COMMIT(); }

        uint32_t ahB = s0 + bi * BUF_BYTES;
        uint32_t alB = ahB + MAT_BYTES;
        uint32_t whB = ahB + 2 * MAT_BYTES;
        uint32_t wlB = ahB + 3 * MAT_BYTES;

#pragma unroll
        for (int ks = 0; ks < 2; ks++) {
            int k0u = ks * 2;
            uint32_t fa_h[4][4], fa_l[4][4];
#pragma unroll
            for (int mi = 0; mi < 4; mi++) {
                uint32_t off = (uint32_t)((wm * 64 + mi * 16 + mrow) * ROWB +
                                          (k0u + mcu) * 16);
                ldm_x4(fa_h[mi], ahB + off);
                ldm_x4(fa_l[mi], alB + off);
            }
            uint32_t fb_h[2][4], fb_l[2][4];
#pragma unroll
            for (int hf = 0; hf < 2; hf++) {
                uint32_t off = (uint32_t)((wn * 32 + hf * 16 + mrow) * ROWB +
                                          (k0u + mcu) * 16);
                ldm_x4(fb_h[hf], whB + off);
                ldm_x4(fb_l[hf], wlB + off);
            }
#pragma unroll
            for (int mi = 0; mi < 4; mi++)
#pragma unroll
                for (int nj = 0; nj < 4; nj++) {
                    int hf = nj >> 1, lo = nj & 1;
                    uint32_t bv[2] = {fb_h[hf][lo], fb_h[hf][lo + 2]};
                    mma_bf16(C[mi][nj], fa_h[mi], bv);
                }
#pragma unroll
            for (int mi = 0; mi < 4; mi++)
#pragma unroll
                for (int nj = 0; nj < 4; nj++) {
                    int hf = nj >> 1, lo = nj & 1;
                    uint32_t bv[2] = {fb_l[hf][lo], fb_l[hf][lo + 2]};
                    mma_bf16(C[mi][nj], fa_h[mi], bv);
                }
#pragma unroll
            for (int mi = 0; mi < 4; mi++)
#pragma unroll
                for (int nj = 0; nj < 4; nj++) {
                    int hf = nj >> 1, lo = nj & 1;
                    uint32_t bv[2] = {fb_h[hf][lo], fb_h[hf][lo + 2]};
                    mma_bf16(C[mi][nj], fa_l[mi], bv);
                }
        }
    }

    // Epilogue
    int g = lane >> 2, t = lane & 3;
#pragma unroll
    for (int mi = 0; mi < 4; mi++) {
#pragma unroll
        for (int nj = 0; nj < 4; nj++) {
            int cbase = col0 + wn * 32 + nj * 8 + t * 2;
#pragma unroll
            for (int rr = 0; rr < 2; rr++) {
                int r = row0 + wm * 64 + mi * 16 + g + rr * 8;
                float vx = C[mi][nj][rr * 2 + 0];
                float vy = C[mi][nj][rr * 2 + 1];
                if (mode == 0) {
                    int b = r >> 11, s = r & 2047, h = cbase >> 6, dd = cbase & 63;
                    if (z < 2) {
                        vx *= g_emb[s * HD + dd];
                        vy *= g_emb[s * HD + dd + 1];
                        if (z == 0) { vx *= 0.125f; vy *= 0.125f; }
                    }
                    __half hx = __float2half(vx);
                    __half hy = __float2half(vy);
                    if (z == 0) {
                        size_t ib = ((size_t)(b * NH + h) * SEQ + s) * HD + dd;
                        *(__half2*)&g_qh[ib] = __half2(hx, hy);
                    } else if (z == 1) {
                        size_t ib = ((size_t)(b * NH + h) * SEQ + s) * HD + dd;
                        *(__half2*)&g_kh[ib] = __half2(hx, hy);
                        *(__half2*)&g_kl[ib] =
                            __floats2half2_rn(vx - __half2float(hx),
                                              vy - __half2float(hy));
                    } else {
                        // transposed V: [b,h,d,s]
                        size_t tb = ((size_t)(b * NH + h) * HD + dd) * SEQ + s;
                        g_vth[tb] = hx;
                        g_vtl[tb] = __float2half(vx - __half2float(hx));
                        g_vth[tb + SEQ] = hy;
                        g_vtl[tb + SEQ] = __float2half(vy - __half2float(hy));
                    }
                } else {
                    float2 bv = *(const float2*)&bias[cbase];
                    float2 xv = *(const float2*)&xres[(size_t)r * D_MODEL + cbase];
                    float2 v;
                    v.x = vx + bv.x + xv.x;
                    v.y = vy + bv.y + xv.y;
                    *(float2*)&outp[(size_t)r * D_MODEL + cbase] = v;
                }
            }
        }
    }
}

// ---------------------------------------------------------------------------
// HMMA fp16 2-term flash attention: 128 q-rows/CTA, 64-key tiles, 8 warps.
// S = Qh*(Kh+Kl)^T;  O += Ph*(Vh+Vl) with V pre-transposed.
// Double-buffered K/V/mask; one __syncthreads per kt; heavy-first qt order.
// Epilogue writes bf16 hi/lo (for the bf16 3-term out-proj).
// ---------------------------------------------------------------------------
#define FP 144                            // smem row pitch bytes (64 fp16 + 8 pad)
#define FQH_B 0
#define KV0_B (128 * FP)                  // 18432
#define KVSTAGE_B (4 * 64 * FP)           // 36864
#define KH_OFF 0
#define KL_OFF (64 * FP)
#define VH_OFF (2 * 64 * FP)
#define VL_OFF (3 * 64 * FP)
#define FMS_B (KV0_B + 2 * KVSTAGE_B)     // 92160
#define FLASH_SMEM (FMS_B + 2 * 64 * 4)   // 92672

__global__ __launch_bounds__(256) void flash_mma_kernel(const unsigned char* __restrict__ kpm) {
    extern __shared__ char fsm[];
    uint32_t s0 = smem_to_u32(fsm);
    float* Ms = (float*)(fsm + FMS_B);

    int tid = threadIdx.x, lane = tid & 31, wid = tid >> 5;
    int qt = (int)gridDim.x - 1 - (int)blockIdx.x;   // heavy tiles first
    int bh = blockIdx.y;            // 0..63
    int b = bh >> 4, h = bh & 15;
    int q0 = qt * 128;

    int g = lane >> 2, t4 = lane & 3;
    int amat = lane >> 3;
    int mrow = (amat & 1) * 8 + (lane & 7);
    int mcu  = amat >> 1;

    auto load_kv = [&](int kt, int stage) {
        int k0 = kt * 64;
        uint32_t kb = s0 + KV0_B + stage * KVSTAGE_B;
#pragma unroll
        for (int t = 0; t < 2; t++) {
            int u = tid + t * 256;      // 0..511
            int r = u >> 3, cu = u & 7;
            size_t ki = ((size_t)bh * SEQ + k0 + r) * HD + cu * 8;
            size_t vi = ((size_t)bh * HD + r) * SEQ + k0 + cu * 8;
            cp_async16(kb + KH_OFF + r * FP + cu * 16, g_kh + ki);
            cp_async16(kb + KL_OFF + r * FP + cu * 16, g_kl + ki);
            cp_async16(kb + VH_OFF + r * FP + cu * 16, g_vth + vi);
            cp_async16(kb + VL_OFF + r * FP + cu * 16, g_vtl + vi);
        }
    };

    // Initial: Q tile (fp16 hi) + KV stage 0 + mask slot 0
#pragma unroll
    for (int t = 0; t < 4; t++) {
        int u = tid + t * 256;          // 0..1023
        int r = u >> 3, cu = u & 7;
        size_t gi = ((size_t)bh * SEQ + q0 + r) * HD + cu * 8;
        cp_async16(s0 + FQH_B + r * FP + cu * 16, g_qh + gi);
    }
    load_kv(0, 0);
    if (tid < 64) Ms[tid] = kpm[b * SEQ + tid] ? -1e30f : 0.f;
    CP_COMMIT();

    float mr[2] = {-INFINITY, -INFINITY};
    float lr[2] = {0.f, 0.f};
    float O[8][4];
#pragma unroll
    for (int j = 0; j < 8; j++)
#pragma unroll
        for (int q = 0; q < 4; q++) O[j][q] = 0.f;

    int rowg = q0 + wid * 16 + g;       // this thread's first q row

    int ktmax = (q0 + 127) >> 6;
    for (int kt = 0; kt <= ktmax; kt++) {
        int bi = kt & 1;
        int k0 = kt * 64;
        CP_WAIT0();
        __syncthreads();
        if (kt < ktmax) {
            load_kv(kt + 1, bi ^ 1);
            CP_COMMIT();
            if (tid < 64)
                Ms[(bi ^ 1) * 64 + tid] =
                    kpm[b * SEQ + (kt + 1) * 64 + tid] ? -1e30f : 0.f;
        }
        uint32_t kvb = s0 + KV0_B + bi * KVSTAGE_B;
        float* Msl = Ms + bi * 64;

        // ---- S = Qh K^T (2-term) ----
        float S[8][4];
#pragma unroll
        for (int j = 0; j < 8; j++)
#pragma unroll
            for (int q = 0; q < 4; q++) S[j][q] = 0.f;

#pragma unroll
        for (int ks = 0; ks < 4; ks++) {
            uint32_t qh[4];
            uint32_t qoff = (uint32_t)((wid * 16 + mrow) * FP + ks * 32 + mcu * 16);
            ldm_x4(qh, s0 + FQH_B + qoff);
            uint32_t kh[4][4], kl[4][4];
#pragma unroll
            for (int grp = 0; grp < 4; grp++) {
                uint32_t koff = (uint32_t)((grp * 16 + mrow) * FP + ks * 32 + mcu * 16);
                ldm_x4(kh[grp], kvb + KH_OFF + koff);
                ldm_x4(kl[grp], kvb + KL_OFF + koff);
            }
#pragma unroll
            for (int j = 0; j < 8; j++) {
                int grp = j >> 1, lo = j & 1;
                uint32_t bv[2] = {kh[grp][lo], kh[grp][lo + 2]};
                mma_f16(S[j], qh, bv);
            }
#pragma unroll
            for (int j = 0; j < 8; j++) {
                int grp = j >> 1, lo = j & 1;
                uint32_t bv[2] = {kl[grp][lo], kl[grp][lo + 2]};
                mma_f16(S[j], qh, bv);
            }
        }

        // ---- mask + row max (no MUFU) ----
        bool needc = (k0 + 63 > q0);
#pragma unroll
        for (int j = 0; j < 8; j++) {
            int c0 = 8 * j + t4 * 2;
            float m0 = Msl[c0], m1 = Msl[c0 + 1];
            float s0v = S[j][0] + m0, s1v = S[j][1] + m1;
            float s2v = S[j][2] + m0, s3v = S[j][3] + m1;
            if (needc) {
                int kc0 = k0 + c0;
                if (kc0 > rowg)          s0v = -1e30f;
                if (kc0 + 1 > rowg)      s1v = -1e30f;
                if (kc0 > rowg + 8)      s2v = -1e30f;
                if (kc0 + 1 > rowg + 8)  s3v = -1e30f;
            }
            S[j][0] = s0v; S[j][1] = s1v; S[j][2] = s2v; S[j][3] = s3v;
        }
        float mt0 = -1e30f, mt1 = -1e30f;
#pragma unroll
        for (int j = 0; j < 8; j++) {
            mt0 = fmaxf(mt0, fmaxf(S[j][0], S[j][1]));
            mt1 = fmaxf(mt1, fmaxf(S[j][2], S[j][3]));
        }
        mt0 = fmaxf(mt0, __shfl_xor_sync(0xffffffffu, mt0, 1));
        mt0 = fmaxf(mt0, __shfl_xor_sync(0xffffffffu, mt0, 2));
        mt1 = fmaxf(mt1, __shfl_xor_sync(0xffffffffu, mt1, 1));
        mt1 = fmaxf(mt1, __shfl_xor_sync(0xffffffffu, mt1, 2));
        float mn0 = fmaxf(mr[0], mt0), mn1 = fmaxf(mr[1], mt1);
        float corr0 = __expf(mr[0] - mn0), corr1 = __expf(mr[1] - mn1);
        mr[0] = mn0; mr[1] = mn1;
#pragma unroll
        for (int j = 0; j < 8; j++) {
            O[j][0] *= corr0; O[j][1] *= corr0;
            O[j][2] *= corr1; O[j][3] *= corr1;
        }

        // ---- interleaved: exp/pack of chunk ks + PV mma (2-term) ----
        float rs0 = 0.f, rs1 = 0.f;
#pragma unroll
        for (int ks = 0; ks < 4; ks++) {
            int j0 = 2 * ks, j1 = 2 * ks + 1;
            float a0 = __expf(S[j0][0] - mn0), a1 = __expf(S[j0][1] - mn0);
            float a2 = __expf(S[j0][2] - mn1), a3 = __expf(S[j0][3] - mn1);
            float b0 = __expf(S[j1][0] - mn0), b1 = __expf(S[j1][1] - mn0);
            float b2 = __expf(S[j1][2] - mn1), b3 = __expf(S[j1][3] - mn1);
            rs0 += a0 + a1 + b0 + b1;
            rs1 += a2 + a3 + b2 + b3;
            uint32_t pah[4];
            pah[0] = pack_f16x2(a0, a1);
            pah[1] = pack_f16x2(a2, a3);
            pah[2] = pack_f16x2(b0, b1);
            pah[3] = pack_f16x2(b2, b3);
            uint32_t vh[4][4], vl[4][4];
#pragma unroll
            for (int grp = 0; grp < 4; grp++) {
                uint32_t voff = (uint32_t)((grp * 16 + mrow) * FP + ks * 32 + mcu * 16);
                ldm_x4(vh[grp], kvb + VH_OFF + voff);
                ldm_x4(vl[grp], kvb + VL_OFF + voff);
            }
#pragma unroll
            for (int jd = 0; jd < 8; jd++) {
                int grp = jd >> 1, lo = jd & 1;
                uint32_t bv[2] = {vh[grp][lo], vh[grp][lo + 2]};
                mma_f16(O[jd], pah, bv);
            }
#pragma unroll
            for (int jd = 0; jd < 8; jd++) {
                int grp = jd >> 1, lo = jd & 1;
                uint32_t bv[2] = {vl[grp][lo], vl[grp][lo + 2]};
                mma_f16(O[jd], pah, bv);
            }
        }

        // row-sum reductions off the critical path
        rs0 += __shfl_xor_sync(0xffffffffu, rs0, 1);
        rs0 += __shfl_xor_sync(0xffffffffu, rs0, 2);
        rs1 += __shfl_xor_sync(0xffffffffu, rs1, 1);
        rs1 += __shfl_xor_sync(0xffffffffu, rs1, 2);
        lr[0] = lr[0] * corr0 + rs0;
        lr[1] = lr[1] * corr1 + rs1;
    }

    // ---- epilogue: normalize, write bf16 hi/lo to [B,S,D] for out-proj ----
    float inv0 = 1.f / lr[0], inv1 = 1.f / lr[1];
#pragma unroll
    for (int j = 0; j < 8; j++) {
        int dd = h * HD + 8 * j + t4 * 2;
        {
            float vx = O[j][0] * inv0, vy = O[j][1] * inv0;
            size_t idx = (size_t)(b * SEQ + rowg) * D_MODEL + dd;
            __nv_bfloat16 hx = __float2bfloat16(vx), hy = __float2bfloat16(vy);
            *(__nv_bfloat162*)&g_ah[idx] = __nv_bfloat162(hx, hy);
            *(__nv_bfloat162*)&g_al[idx] =
                __nv_bfloat162(__float2bfloat16(vx - __bfloat162float(hx)),
                               __float2bfloat16(vy - __bfloat162float(hy)));
        }
        {
            float vx = O[j][2] * inv1, vy = O[j][3] * inv1;
            size_t idx = (size_t)(b * SEQ + rowg + 8) * D_MODEL + dd;
            __nv_bfloat16 hx = __float2bfloat16(vx), hy = __float2bfloat16(vy);
            *(__nv_bfloat162*)&g_ah[idx] = __nv_bfloat162(hx, hy);
            *(__nv_bfloat162*)&g_al[idx] =
                __nv_bfloat162(__float2bfloat16(vx - __bfloat162float(hx)),
                               __float2bfloat16(vy - __bfloat162float(hy)));
        }
    }
}

// ---------------------------------------------------------------------------
extern "C" void kernel_launch(void* const* d_in, const int* in_sizes, int n_in,
                              void* d_out, int out_size) {
    const float* x            = (const float*)d_in[0];
    const unsigned char* kpm  = (const unsigned char*)d_in[1];
    const float* q_w          = (const float*)d_in[2];
    const float* k_w          = (const float*)d_in[3];
    const float* v_w          = (const float*)d_in[4];
    const float* out_w        = (const float*)d_in[5];
    const float* out_b        = (const float*)d_in[6];
    const float* ln_g         = (const float*)d_in[7];
    const float* ln_b         = (const float*)d_in[8];
    float* out = (float*)d_out;

    cudaFuncSetAttribute(flash_mma_kernel, cudaFuncAttributeMaxDynamicSharedMemorySize, FLASH_SMEM);
    cudaFuncSetAttribute(mma_gemm_kernel, cudaFuncAttributeMaxDynamicSharedMemorySize, GEMM_SMEM);

    emb_kernel<<<(SEQ * HD) / 256, 256>>>();
    wconv_kernel<<<(4 * D_MODEL * D_MODEL) / 256, 256>>>(q_w, k_w, v_w, out_w);
    ln_kernel<<<ROWS, 256>>>(x, ln_g, ln_b);
    mma_gemm_kernel<<<dim3(D_MODEL / BN, ROWS / BM, 3), 256, GEMM_SMEM>>>(
        0, nullptr, nullptr, nullptr);
    flash_mma_kernel<<<dim3(16, 64), 256, FLASH_SMEM>>>(kpm);
    mma_gemm_kernel<<<dim3(D_MODEL / BN, ROWS / BM, 1), 256, GEMM_SMEM>>>(
        1, out_b, x, out);
}